// round 1
// baseline (speedup 1.0000x reference)
#include <cuda_runtime.h>
#include <math.h>

#define NB 2048

// ---------------- scratch (static device globals: allocation-rule safe) ----------------
__device__ float g_buf1[NB*16*28*28];   // conv1 raw out
__device__ float g_buf2[NB*16*28*28];   // conv2 raw out
__device__ float g_buf3[NB*16*14*14];   // pooled act2
__device__ float g_buf4[NB*32*14*14];   // conv3 raw out
__device__ float g_buf5[NB*32*14*14];   // conv4 raw out
__device__ float g_buf6[NB*32*7*7];     // pooled act4
__device__ float g_buf7[NB*64*7*7];     // conv5 raw out
__device__ float g_buf8[NB*64*7*7];     // conv6 raw out
__device__ float g_buf9[NB*64*4*4];     // pooled act6
__device__ float g_rk1[16*1*9];
__device__ float g_rk2[16*16*9];
__device__ float g_rk3[32*16*9];
__device__ float g_sum[224];
__device__ float g_sumsq[224];
__device__ float g_scale[224];
__device__ float g_shift[224];
__device__ float g_nms;

// stat array offsets per layer
#define S1 0
#define S2 16
#define S3 32
#define S4 64
#define S5 96
#define S6 160

// ---------------- small helpers ----------------
__device__ __forceinline__ float warp_sum(float v) {
    #pragma unroll
    for (int o = 16; o > 0; o >>= 1) v += __shfl_xor_sync(0xffffffffu, v, o);
    return v;
}

// ---------------- zero accumulators ----------------
__global__ void k_zero() {
    int t = threadIdx.x;
    for (int i = t; i < 224; i += blockDim.x) { g_sum[i] = 0.f; g_sumsq[i] = 0.f; }
    if (t == 0) g_nms = 0.f;
}

// ---------------- build rotated kernels ----------------
// torch cal_rot_pad semantics: tap (x=col-1, y=row-1), rotated by th=2*pi*i/8,
// rounded; scattered to kernel position (1 - y_rot, 1 - x_rot). Non-separate
// layers roll the r input-channel blocks by i: src block = (b - i) mod 8.
__global__ void k_build_rk(const float* __restrict__ w1, const float* __restrict__ w2,
                           const float* __restrict__ w3) {
    int idx = blockIdx.x * blockDim.x + threadIdx.x;
    if (idx >= 16 + 256 + 512) return;
    float local[9];
    #pragma unroll
    for (int k = 0; k < 9; k++) local[k] = 0.f;

    int i, a, ic = 0, which;
    if (idx < 16)       { which = 0; i = idx >> 1; a = idx & 1; }
    else if (idx < 272) { int e = idx - 16;  which = 1; ic = e & 15; a = (e >> 4) & 1; i = e >> 5; }
    else                { int e = idx - 272; which = 2; ic = e & 15; a = (e >> 4) & 3; i = e >> 6; }

    double th = 0.78539816339744831 * (double)i;   // 2*pi/8 * i
    double ct = cos(th), st = sin(th);

    int ics = ic;
    if (which != 0) {   // non-separate: roll input blocks (cin/r = 2)
        int bnew = ic >> 1, sub = ic & 1;
        int bsrc = ((bnew - i) % 8 + 8) % 8;
        ics = bsrc * 2 + sub;
    }
    const float* src;
    if (which == 0)      src = w1 + a * 9;
    else if (which == 1) src = w2 + (a * 16 + ics) * 9;
    else                 src = w3 + (a * 16 + ics) * 9;

    #pragma unroll
    for (int t = 0; t < 9; t++) {
        int row = t / 3, col = t % 3;
        double x = (double)(col - 1), y = (double)(row - 1);
        int xr = (int)llrint(x * ct + y * st);
        int yr = (int)llrint(-x * st + y * ct);
        local[(1 - yr) * 3 + (1 - xr)] += src[t];
    }

    float* dst;
    if (which == 0)      dst = g_rk1 + (i * 2 + a) * 9;
    else if (which == 1) dst = g_rk2 + ((i * 2 + a) * 16 + ic) * 9;
    else                 dst = g_rk3 + ((i * 4 + a) * 16 + ic) * 9;
    #pragma unroll
    for (int k = 0; k < 9; k++) dst[k] = local[k];
}

// ---------------- direct 3x3 conv, one image per block ----------------
// Optional fused input normalization: relu(x*scale[c] + shift[c]).
template<int CIN, int COUT, int H, int W, int OCB, bool BN_IN>
__global__ __launch_bounds__(256)
void conv3x3(const float* __restrict__ in, const float* __restrict__ wt,
             const float* __restrict__ scale, const float* __restrict__ shift,
             float* __restrict__ out) {
    constexpr int HP = H + 2, WP = W + 2, P = H * W, NOCG = COUT / OCB;
    extern __shared__ float sm[];
    float* s_in = sm;                         // CIN * HP * WP
    float* s_w  = sm + CIN * HP * WP;         // CIN * COUT * 9, layout [ic][oc][9]

    const int b = blockIdx.x;
    const int tid = threadIdx.x;

    for (int idx = tid; idx < CIN * COUT * 9; idx += blockDim.x) {
        int k = idx % 9, oc = (idx / 9) % COUT, ic = idx / (9 * COUT);
        s_w[(ic * COUT + oc) * 9 + k] = wt[(oc * CIN + ic) * 9 + k];
    }
    const float* inb = in + (size_t)b * CIN * H * W;
    for (int idx = tid; idx < CIN * HP * WP; idx += blockDim.x) {
        int ic  = idx / (HP * WP);
        int rem = idx - ic * (HP * WP);
        int r = rem / WP, c = rem - r * WP;
        float v = 0.f;
        if (r >= 1 && r <= H && c >= 1 && c <= W) {
            v = inb[(ic * H + (r - 1)) * W + (c - 1)];
            if (BN_IN) v = fmaxf(0.f, fmaf(v, scale[ic], shift[ic]));
        }
        s_in[idx] = v;
    }
    __syncthreads();

    float* outb = out + (size_t)b * COUT * H * W;
    for (int item = tid; item < NOCG * P; item += blockDim.x) {
        int ocg = item / P;
        int pix = item - ocg * P;
        int py = pix / W, px = pix - py * W;
        int oc0 = ocg * OCB;
        float acc[OCB];
        #pragma unroll
        for (int k = 0; k < OCB; k++) acc[k] = 0.f;

        #pragma unroll 2
        for (int ic = 0; ic < CIN; ic++) {
            const float* ip = s_in + (ic * HP + py) * WP + px;
            float i0 = ip[0],        i1 = ip[1],        i2 = ip[2];
            float i3 = ip[WP],       i4 = ip[WP + 1],   i5 = ip[WP + 2];
            float i6 = ip[2 * WP],   i7 = ip[2 * WP + 1], i8 = ip[2 * WP + 2];
            const float* wp = s_w + (ic * COUT + oc0) * 9;
            #pragma unroll
            for (int k = 0; k < OCB; k++) {
                const float* w9 = wp + k * 9;
                float a = acc[k];
                a = fmaf(i0, w9[0], a); a = fmaf(i1, w9[1], a); a = fmaf(i2, w9[2], a);
                a = fmaf(i3, w9[3], a); a = fmaf(i4, w9[4], a); a = fmaf(i5, w9[5], a);
                a = fmaf(i6, w9[6], a); a = fmaf(i7, w9[7], a); a = fmaf(i8, w9[8], a);
                acc[k] = a;
            }
        }
        #pragma unroll
        for (int k = 0; k < OCB; k++)
            outb[(oc0 + k) * P + pix] = acc[k];
    }
}

// ---------------- per-channel sum / sumsq over raw conv output ----------------
__global__ void k_stats(const float* __restrict__ x, float* __restrict__ sum,
                        float* __restrict__ sumsq, int C, int HW) {
    int c = blockIdx.y;
    float s = 0.f, s2 = 0.f;
    int N = NB * HW;
    for (int idx = blockIdx.x * blockDim.x + threadIdx.x; idx < N;
         idx += gridDim.x * blockDim.x) {
        int b = idx / HW; int p = idx - b * HW;
        float v = x[((size_t)b * C + c) * HW + p];
        s += v; s2 = fmaf(v, v, s2);
    }
    s = warp_sum(s); s2 = warp_sum(s2);
    __shared__ float sh[2][8];
    int lane = threadIdx.x & 31, wid = threadIdx.x >> 5;
    if (lane == 0) { sh[0][wid] = s; sh[1][wid] = s2; }
    __syncthreads();
    if (threadIdx.x == 0) {
        float a = 0.f, b2 = 0.f;
        #pragma unroll
        for (int i = 0; i < 8; i++) { a += sh[0][i]; b2 += sh[1][i]; }
        atomicAdd(&sum[c], a); atomicAdd(&sumsq[c], b2);
    }
}

// gmod: gamma/beta are shared across rotation groups (index = c % gmod)
__global__ void k_finalize(const float* __restrict__ sum, const float* __restrict__ sumsq,
                           const float* __restrict__ gamma, const float* __restrict__ beta,
                           float* __restrict__ scale, float* __restrict__ shift,
                           int C, int gmod, float invN) {
    int c = threadIdx.x;
    if (c >= C) return;
    float mean = sum[c] * invN;
    float var  = sumsq[c] * invN - mean * mean;
    float sc = gamma[c % gmod] * rsqrtf(var + 1e-5f);
    scale[c] = sc;
    shift[c] = beta[c % gmod] - mean * sc;
}

// ---------------- BN + ReLU + 2x2 maxpool (stride 2, optional pad 1) ----------------
template<int C, int H, int W, int PAD>
__global__ void k_pool(const float* __restrict__ in, const float* __restrict__ scale,
                       const float* __restrict__ shift, float* __restrict__ out) {
    constexpr int HO = (H + 2 * PAD) / 2, WO = (W + 2 * PAD) / 2;
    int total = NB * C * HO * WO;
    for (int idx = blockIdx.x * blockDim.x + threadIdx.x; idx < total;
         idx += gridDim.x * blockDim.x) {
        int wo = idx % WO; int t = idx / WO;
        int ho = t % HO; t /= HO;
        int c = t % C; int b = t / C;
        const float* p = in + ((size_t)b * C + c) * (H * W);
        float sc = scale[c], sh = shift[c];
        float m = -1e30f;
        int iy0 = ho * 2 - PAD, ix0 = wo * 2 - PAD;
        #pragma unroll
        for (int dy = 0; dy < 2; dy++) {
            int iy = iy0 + dy; if (iy < 0 || iy >= H) continue;
            #pragma unroll
            for (int dx = 0; dx < 2; dx++) {
                int ix = ix0 + dx; if (ix < 0 || ix >= W) continue;
                float v = fmaxf(0.f, fmaf(p[iy * W + ix], sc, sh));
                if (v > m) m = v;
            }
        }
        out[idx] = m;
    }
}

// ---------------- NMS reduction on act3 (rotation-MINOR channel view c=c1*8+j) ------
__global__ void k_nms(const float* __restrict__ x, const float* __restrict__ scale,
                      const float* __restrict__ shift, float* __restrict__ nms_sum) {
    const int HW = 196;
    int total = NB * 4 * HW;
    float local = 0.f;
    for (int idx = blockIdx.x * blockDim.x + threadIdx.x; idx < total;
         idx += gridDim.x * blockDim.x) {
        int p = idx % HW; int t = idx / HW;
        int c1 = t % 4; int b = t / 4;
        const float* base = x + ((size_t)b * 32 + c1 * 8) * HW + p;
        float v[8]; float m = -1e30f;
        #pragma unroll
        for (int j = 0; j < 8; j++) {
            int c = c1 * 8 + j;
            float u = fmaxf(0.f, fmaf(base[j * HW], scale[c], shift[c]));
            v[j] = u; if (u > m) m = u;
        }
        float s = 0.f;
        #pragma unroll
        for (int j = 0; j < 8; j++) if (v[j] != m) s += v[j];
        local += s;
    }
    local = warp_sum(local);
    __shared__ float sh[8];
    int lane = threadIdx.x & 31, wid = threadIdx.x >> 5;
    if (lane == 0) sh[wid] = local;
    __syncthreads();
    if (threadIdx.x == 0) {
        float a = 0.f;
        #pragma unroll
        for (int i = 0; i < 8; i++) a += sh[i];
        atomicAdd(nms_sum, a);
    }
}

// ---------------- conv7 (4x4, pad 2) + bias + global maxpool + NMS scalar -----------
__global__ __launch_bounds__(256)
void k_conv7(const float* __restrict__ in, const float* __restrict__ w7,
             const float* __restrict__ b7, const float* __restrict__ nms_sum,
             float* __restrict__ out, int out_size) {
    __shared__ float s_in[64 * 16];
    __shared__ float s_w[10 * 64 * 16];
    __shared__ float s_res[250];
    __shared__ float s_b[10];
    int b = blockIdx.x, tid = threadIdx.x;
    for (int i = tid; i < 64 * 16; i += 256) s_in[i] = in[(size_t)b * 64 * 16 + i];
    for (int i = tid; i < 10 * 64 * 16; i += 256) s_w[i] = w7[i];
    if (tid < 10) s_b[tid] = b7[tid];
    __syncthreads();

    for (int item = tid; item < 250; item += 256) {
        int oc = item / 25; int pix = item % 25;
        int oy = pix / 5, ox = pix % 5;
        float a = 0.f;
        for (int ic = 0; ic < 64; ic++) {
            const float* ip = s_in + ic * 16;
            const float* wp = s_w + (oc * 64 + ic) * 16;
            #pragma unroll
            for (int ky = 0; ky < 4; ky++) {
                int iy = oy + ky - 2; if (iy < 0 || iy > 3) continue;
                #pragma unroll
                for (int kx = 0; kx < 4; kx++) {
                    int ix = ox + kx - 2; if (ix < 0 || ix > 3) continue;
                    a = fmaf(ip[iy * 4 + ix], wp[ky * 4 + kx], a);
                }
            }
        }
        s_res[item] = a;
    }
    __syncthreads();
    if (tid < 10) {
        float m = -1e30f;
        #pragma unroll
        for (int p = 0; p < 25; p++) m = fmaxf(m, s_res[tid * 25 + p]);
        out[b * 10 + tid] = m + s_b[tid];
    }
    if (b == 0 && tid == 0)
        out[out_size - 1] = nms_sum[0] * (1.0f / 12845056.0f);  // mean over 2048*32*196
}

// ---------------- launch ----------------
extern "C" void kernel_launch(void* const* d_in, const int* in_sizes, int n_in,
                              void* d_out, int out_size) {
    const float* x   = (const float*)d_in[0];
    const float* w1  = (const float*)d_in[1];
    const float* w2  = (const float*)d_in[2];
    const float* w3  = (const float*)d_in[3];
    const float* w4  = (const float*)d_in[4];
    const float* w5  = (const float*)d_in[5];
    const float* w6  = (const float*)d_in[6];
    const float* w7  = (const float*)d_in[7];
    const float* g1  = (const float*)d_in[8];
    const float* b1  = (const float*)d_in[9];
    const float* g2  = (const float*)d_in[10];
    const float* b2  = (const float*)d_in[11];
    const float* g3  = (const float*)d_in[12];
    const float* b3  = (const float*)d_in[13];
    const float* g4  = (const float*)d_in[14];
    const float* b4  = (const float*)d_in[15];
    const float* g5  = (const float*)d_in[16];
    const float* b5  = (const float*)d_in[17];
    const float* g6  = (const float*)d_in[18];
    const float* b6  = (const float*)d_in[19];
    const float* b7  = (const float*)d_in[20];
    float* out = (float*)d_out;

    float *buf1, *buf2, *buf3, *buf4, *buf5, *buf6, *buf7, *buf8, *buf9;
    float *rk1, *rk2, *rk3, *psum, *psumsq, *pscale, *pshift, *pnms;
    cudaGetSymbolAddress((void**)&buf1, g_buf1);
    cudaGetSymbolAddress((void**)&buf2, g_buf2);
    cudaGetSymbolAddress((void**)&buf3, g_buf3);
    cudaGetSymbolAddress((void**)&buf4, g_buf4);
    cudaGetSymbolAddress((void**)&buf5, g_buf5);
    cudaGetSymbolAddress((void**)&buf6, g_buf6);
    cudaGetSymbolAddress((void**)&buf7, g_buf7);
    cudaGetSymbolAddress((void**)&buf8, g_buf8);
    cudaGetSymbolAddress((void**)&buf9, g_buf9);
    cudaGetSymbolAddress((void**)&rk1, g_rk1);
    cudaGetSymbolAddress((void**)&rk2, g_rk2);
    cudaGetSymbolAddress((void**)&rk3, g_rk3);
    cudaGetSymbolAddress((void**)&psum, g_sum);
    cudaGetSymbolAddress((void**)&psumsq, g_sumsq);
    cudaGetSymbolAddress((void**)&pscale, g_scale);
    cudaGetSymbolAddress((void**)&pshift, g_shift);
    cudaGetSymbolAddress((void**)&pnms, g_nms);

    // dynamic smem opt-ins
    cudaFuncSetAttribute(conv3x3<16,16,28,28,16,true>,  cudaFuncAttributeMaxDynamicSharedMemorySize, 66816);
    cudaFuncSetAttribute(conv3x3<32,32,14,14,16,true>,  cudaFuncAttributeMaxDynamicSharedMemorySize, 69632);
    cudaFuncSetAttribute(conv3x3<32,64,7,7,16,false>,   cudaFuncAttributeMaxDynamicSharedMemorySize, 84096);
    cudaFuncSetAttribute(conv3x3<64,64,7,7,16,true>,    cudaFuncAttributeMaxDynamicSharedMemorySize, 168192);

    const float invN784 = 1.0f / (2048.0f * 784.0f);
    const float invN196 = 1.0f / (2048.0f * 196.0f);
    const float invN49  = 1.0f / (2048.0f * 49.0f);

    k_zero<<<1, 256>>>();
    k_build_rk<<<4, 256>>>(w1, w2, w3);

    // layer 1: conv1 (rotated, separate) on raw x
    conv3x3<1,16,28,28,16,false><<<NB, 256, (1*30*30 + 1*16*9) * 4>>>(x, rk1, nullptr, nullptr, buf1);
    k_stats<<<dim3(64, 16), 256>>>(buf1, psum + S1, psumsq + S1, 16, 784);
    k_finalize<<<1, 16>>>(psum + S1, psumsq + S1, g1, b1, pscale + S1, pshift + S1, 16, 2, invN784);

    // layer 2: conv2 with fused bn1+relu on input
    conv3x3<16,16,28,28,16,true><<<NB, 256, 66816>>>(buf1, rk2, pscale + S1, pshift + S1, buf2);
    k_stats<<<dim3(64, 16), 256>>>(buf2, psum + S2, psumsq + S2, 16, 784);
    k_finalize<<<1, 16>>>(psum + S2, psumsq + S2, g2, b2, pscale + S2, pshift + S2, 16, 2, invN784);

    // bn2+relu+pool -> buf3 [2048,16,14,14]
    k_pool<16,28,28,0><<<4096, 256>>>(buf2, pscale + S2, pshift + S2, buf3);

    // layer 3
    conv3x3<16,32,14,14,16,false><<<NB, 256, (16*16*16 + 16*32*9) * 4>>>(buf3, rk3, nullptr, nullptr, buf4);
    k_stats<<<dim3(64, 32), 256>>>(buf4, psum + S3, psumsq + S3, 32, 196);
    k_finalize<<<1, 32>>>(psum + S3, psumsq + S3, g3, b3, pscale + S3, pshift + S3, 32, 4, invN196);

    // nms on act3
    k_nms<<<1024, 256>>>(buf4, pscale + S3, pshift + S3, pnms);

    // layer 4: conv4 with fused bn3+relu on input
    conv3x3<32,32,14,14,16,true><<<NB, 256, 69632>>>(buf4, w4, pscale + S3, pshift + S3, buf5);
    k_stats<<<dim3(64, 32), 256>>>(buf5, psum + S4, psumsq + S4, 32, 196);
    k_finalize<<<1, 32>>>(psum + S4, psumsq + S4, g4, b4, pscale + S4, pshift + S4, 32, 32, invN196);

    // bn4+relu+pool -> buf6 [2048,32,7,7]
    k_pool<32,14,14,0><<<2048, 256>>>(buf5, pscale + S4, pshift + S4, buf6);

    // layer 5
    conv3x3<32,64,7,7,16,false><<<NB, 256, 84096>>>(buf6, w5, nullptr, nullptr, buf7);
    k_stats<<<dim3(64, 64), 256>>>(buf7, psum + S5, psumsq + S5, 64, 49);
    k_finalize<<<1, 64>>>(psum + S5, psumsq + S5, g5, b5, pscale + S5, pshift + S5, 64, 64, invN49);

    // layer 6: conv6 with fused bn5+relu on input
    conv3x3<64,64,7,7,16,true><<<NB, 256, 168192>>>(buf7, w6, pscale + S5, pshift + S5, buf8);
    k_stats<<<dim3(64, 64), 256>>>(buf8, psum + S6, psumsq + S6, 64, 49);
    k_finalize<<<1, 64>>>(psum + S6, psumsq + S6, g6, b6, pscale + S6, pshift + S6, 64, 64, invN49);

    // bn6+relu+pool(pad=1) -> buf9 [2048,64,4,4]
    k_pool<64,7,7,1><<<1024, 256>>>(buf8, pscale + S6, pshift + S6, buf9);

    // conv7 + bias + global maxpool + nms scalar
    k_conv7<<<NB, 256>>>(buf9, w7, b7, pnms, out, out_size);
}

// round 2
// speedup vs baseline: 1.3331x; 1.3331x over previous
#include <cuda_runtime.h>
#include <math.h>

#define NB 2048

typedef unsigned long long u64;

// ---------------- scratch (static device globals: allocation-rule safe) ----------------
__device__ float g_buf1[NB*16*28*28];   // conv1 raw out
__device__ float g_buf2[NB*16*28*28];   // conv2 raw out
__device__ float g_buf3[NB*16*14*14];   // pooled act2
__device__ float g_buf4[NB*32*14*14];   // conv3 raw out
__device__ float g_buf5[NB*32*14*14];   // conv4 raw out
__device__ float g_buf6[NB*32*7*7];     // pooled act4
__device__ float g_buf7[NB*64*7*7];     // conv5 raw out
__device__ float g_buf8[NB*64*7*7];     // conv6 raw out
__device__ float g_buf9[NB*64*4*4];     // pooled act6
__device__ float g_rk1[16*1*9];
__device__ float g_rk2[16*16*9];
__device__ float g_rk3[32*16*9];
__device__ float g_sum[224];
__device__ float g_sumsq[224];
__device__ float g_scale[224];
__device__ float g_shift[224];
__device__ float g_nms;

#define S1 0
#define S2 16
#define S3 32
#define S4 64
#define S5 96
#define S6 160

// ---------------- packed fp32x2 helpers (Blackwell FFMA2 via PTX) ----------------
__device__ __forceinline__ u64 pack2(float lo, float hi) {
    u64 r; asm("mov.b64 %0, {%1, %2};" : "=l"(r) : "f"(lo), "f"(hi)); return r;
}
__device__ __forceinline__ u64 fma2(u64 a, u64 b, u64 c) {
    u64 d; asm("fma.rn.f32x2 %0, %1, %2, %3;" : "=l"(d) : "l"(a), "l"(b), "l"(c)); return d;
}
__device__ __forceinline__ void unpack2(u64 v, float& lo, float& hi) {
    asm("mov.b64 {%0, %1}, %2;" : "=f"(lo), "=f"(hi) : "l"(v));
}

__device__ __forceinline__ float warp_sum(float v) {
    #pragma unroll
    for (int o = 16; o > 0; o >>= 1) v += __shfl_xor_sync(0xffffffffu, v, o);
    return v;
}

// ---------------- zero accumulators ----------------
__global__ void k_zero() {
    int t = threadIdx.x;
    for (int i = t; i < 224; i += blockDim.x) { g_sum[i] = 0.f; g_sumsq[i] = 0.f; }
    if (t == 0) g_nms = 0.f;
}

// ---------------- build rotated kernels ----------------
__global__ void k_build_rk(const float* __restrict__ w1, const float* __restrict__ w2,
                           const float* __restrict__ w3) {
    int idx = blockIdx.x * blockDim.x + threadIdx.x;
    if (idx >= 16 + 256 + 512) return;
    float local[9];
    #pragma unroll
    for (int k = 0; k < 9; k++) local[k] = 0.f;

    int i, a, ic = 0, which;
    if (idx < 16)       { which = 0; i = idx >> 1; a = idx & 1; }
    else if (idx < 272) { int e = idx - 16;  which = 1; ic = e & 15; a = (e >> 4) & 1; i = e >> 5; }
    else                { int e = idx - 272; which = 2; ic = e & 15; a = (e >> 4) & 3; i = e >> 6; }

    double th = 0.78539816339744831 * (double)i;
    double ct = cos(th), st = sin(th);

    int ics = ic;
    if (which != 0) {
        int bnew = ic >> 1, sub = ic & 1;
        int bsrc = ((bnew - i) % 8 + 8) % 8;
        ics = bsrc * 2 + sub;
    }
    const float* src;
    if (which == 0)      src = w1 + a * 9;
    else if (which == 1) src = w2 + (a * 16 + ics) * 9;
    else                 src = w3 + (a * 16 + ics) * 9;

    #pragma unroll
    for (int t = 0; t < 9; t++) {
        int row = t / 3, col = t % 3;
        double x = (double)(col - 1), y = (double)(row - 1);
        int xr = (int)llrint(x * ct + y * st);
        int yr = (int)llrint(-x * st + y * ct);
        local[(1 - yr) * 3 + (1 - xr)] += src[t];
    }

    float* dst;
    if (which == 0)      dst = g_rk1 + (i * 2 + a) * 9;
    else if (which == 1) dst = g_rk2 + ((i * 2 + a) * 16 + ic) * 9;
    else                 dst = g_rk3 + ((i * 4 + a) * 16 + ic) * 9;
    #pragma unroll
    for (int k = 0; k < 9; k++) dst[k] = local[k];
}

// ---------------- packed-fp32 direct 3x3 conv ----------------
// Thread tile: 4 pixels (one row group) x 8 output channels as 4 oc-PAIRS.
// FMA2 pairs over oc: weight float2 {w[2k],w[2k+1]} loaded with one LDS.64
// (no ALU pack); input value duplicated {v,v} once per tap-column (18 packs/ic
// amortized over 144 FMA2). Optional fused BN+ReLU on input load.
template<int CIN, int COUT, int H, int W, int IMGS, bool BN_IN>
__global__ __launch_bounds__(256)
void conv3x3f2(const float* __restrict__ in, const float* __restrict__ wt,
               const float* __restrict__ scale, const float* __restrict__ shift,
               float* __restrict__ out) {
    constexpr int G  = (W + 3) / 4;      // 4-pixel groups per row
    constexpr int WP = 4 * G + 2;        // padded width (zeros beyond W)
    constexpr int HP = H + 2;
    constexpr int OCG = COUT / 8;
    constexpr int GH = G * H;
    constexpr int ITEMS = IMGS * OCG * GH;
    constexpr int P = H * W;
    constexpr int WFLOATS = CIN * COUT * 9;

    extern __shared__ float sm[];
    float* s_in = sm;                          // IMGS*CIN*HP*WP
    float* s_w  = sm + IMGS * CIN * HP * WP;   // float2 pairs: [ic][oc/2][9]{lo,hi}

    const int b0 = blockIdx.x * IMGS;
    const int tid = threadIdx.x;

    // weights -> interleaved oc-pair layout
    for (int idx = tid; idx < WFLOATS; idx += 256) {
        int h = idx & 1; int u = idx >> 1;
        int t = u % 9; u /= 9;
        int op = u % (COUT / 2); int ic = u / (COUT / 2);
        s_w[idx] = wt[((2 * op + h) * CIN + ic) * 9 + t];
    }
    // inputs (zero padded), fused bn+relu
    for (int idx = tid; idx < IMGS * CIN * HP * WP; idx += 256) {
        int c = idx % WP; int t = idx / WP;
        int r = t % HP; t /= HP;
        int ic = t % CIN; int img = t / CIN;
        float v = 0.f;
        if (r >= 1 && r <= H && c >= 1 && c <= W) {
            v = in[(((size_t)(b0 + img) * CIN + ic) * H + (r - 1)) * W + (c - 1)];
            if (BN_IN) v = fmaxf(0.f, fmaf(v, scale[ic], shift[ic]));
        }
        s_in[idx] = v;
    }
    __syncthreads();

    const u64* w64 = (const u64*)s_w;

    for (int item = tid; item < ITEMS; item += 256) {
        int g = item % GH; int t = item / GH;
        int ocg = t % OCG; int img = t / OCG;
        int gy = g / G, gx = g % G;

        u64 acc[4][4];   // [pixel][oc-pair]
        #pragma unroll
        for (int px = 0; px < 4; px++)
            #pragma unroll
            for (int op = 0; op < 4; op++) acc[px][op] = 0ull;

        const float* ibase = s_in + ((img * CIN) * HP + gy) * WP + 4 * gx;
        const u64* wbase = w64 + (size_t)ocg * 4 * 9;

        for (int ic = 0; ic < CIN; ic++) {
            const float* ip = ibase + ic * HP * WP;
            const u64* wrow = wbase + (size_t)ic * (COUT / 2) * 9;
            #pragma unroll
            for (int r = 0; r < 3; r++) {
                float i0 = ip[r * WP + 0], i1 = ip[r * WP + 1], i2 = ip[r * WP + 2];
                float i3 = ip[r * WP + 3], i4 = ip[r * WP + 4], i5 = ip[r * WP + 5];
                u64 d0 = pack2(i0, i0), d1 = pack2(i1, i1), d2 = pack2(i2, i2);
                u64 d3 = pack2(i3, i3), d4 = pack2(i4, i4), d5 = pack2(i5, i5);
                #pragma unroll
                for (int op = 0; op < 4; op++) {
                    const u64* w9 = wrow + op * 9 + r * 3;
                    u64 w;
                    w = w9[0];
                    acc[0][op] = fma2(d0, w, acc[0][op]);
                    acc[1][op] = fma2(d1, w, acc[1][op]);
                    acc[2][op] = fma2(d2, w, acc[2][op]);
                    acc[3][op] = fma2(d3, w, acc[3][op]);
                    w = w9[1];
                    acc[0][op] = fma2(d1, w, acc[0][op]);
                    acc[1][op] = fma2(d2, w, acc[1][op]);
                    acc[2][op] = fma2(d3, w, acc[2][op]);
                    acc[3][op] = fma2(d4, w, acc[3][op]);
                    w = w9[2];
                    acc[0][op] = fma2(d2, w, acc[0][op]);
                    acc[1][op] = fma2(d3, w, acc[1][op]);
                    acc[2][op] = fma2(d4, w, acc[2][op]);
                    acc[3][op] = fma2(d5, w, acc[3][op]);
                }
            }
        }

        float* outb = out + ((size_t)(b0 + img) * COUT + ocg * 8) * P + gy * W + 4 * gx;
        int px0 = 4 * gx;
        #pragma unroll
        for (int op = 0; op < 4; op++) {
            #pragma unroll
            for (int px = 0; px < 4; px++) {
                if (px0 + px < W) {
                    float lo, hi;
                    unpack2(acc[px][op], lo, hi);
                    outb[(2 * op) * P + px]     = lo;
                    outb[(2 * op + 1) * P + px] = hi;
                }
            }
        }
    }
}

// ---------------- per-channel stats (vectorized, HW % 4 == 0) ----------------
__global__ void k_stats4(const float* __restrict__ x, float* __restrict__ sum,
                         float* __restrict__ sumsq, int C, int HW4) {
    int c = blockIdx.y;
    float s = 0.f, s2 = 0.f;
    int N4 = NB * HW4;
    const float4* xp = (const float4*)x;
    for (int idx = blockIdx.x * blockDim.x + threadIdx.x; idx < N4;
         idx += gridDim.x * blockDim.x) {
        int b = idx / HW4; int p = idx - b * HW4;
        float4 v = xp[(size_t)(b * C + c) * HW4 + p];
        s += (v.x + v.y) + (v.z + v.w);
        s2 = fmaf(v.x, v.x, s2); s2 = fmaf(v.y, v.y, s2);
        s2 = fmaf(v.z, v.z, s2); s2 = fmaf(v.w, v.w, s2);
    }
    s = warp_sum(s); s2 = warp_sum(s2);
    __shared__ float sh[2][8];
    int lane = threadIdx.x & 31, wid = threadIdx.x >> 5;
    if (lane == 0) { sh[0][wid] = s; sh[1][wid] = s2; }
    __syncthreads();
    if (threadIdx.x == 0) {
        float a = 0.f, b2 = 0.f;
        #pragma unroll
        for (int i = 0; i < 8; i++) { a += sh[0][i]; b2 += sh[1][i]; }
        atomicAdd(&sum[c], a); atomicAdd(&sumsq[c], b2);
    }
}

// scalar fallback (HW = 49)
__global__ void k_stats(const float* __restrict__ x, float* __restrict__ sum,
                        float* __restrict__ sumsq, int C, int HW) {
    int c = blockIdx.y;
    float s = 0.f, s2 = 0.f;
    int N = NB * HW;
    for (int idx = blockIdx.x * blockDim.x + threadIdx.x; idx < N;
         idx += gridDim.x * blockDim.x) {
        int b = idx / HW; int p = idx - b * HW;
        float v = x[((size_t)b * C + c) * HW + p];
        s += v; s2 = fmaf(v, v, s2);
    }
    s = warp_sum(s); s2 = warp_sum(s2);
    __shared__ float sh[2][8];
    int lane = threadIdx.x & 31, wid = threadIdx.x >> 5;
    if (lane == 0) { sh[0][wid] = s; sh[1][wid] = s2; }
    __syncthreads();
    if (threadIdx.x == 0) {
        float a = 0.f, b2 = 0.f;
        #pragma unroll
        for (int i = 0; i < 8; i++) { a += sh[0][i]; b2 += sh[1][i]; }
        atomicAdd(&sum[c], a); atomicAdd(&sumsq[c], b2);
    }
}

__global__ void k_finalize(const float* __restrict__ sum, const float* __restrict__ sumsq,
                           const float* __restrict__ gamma, const float* __restrict__ beta,
                           float* __restrict__ scale, float* __restrict__ shift,
                           int C, int gmod, float invN) {
    int c = threadIdx.x;
    if (c >= C) return;
    float mean = sum[c] * invN;
    float var  = sumsq[c] * invN - mean * mean;
    float sc = gamma[c % gmod] * rsqrtf(var + 1e-5f);
    scale[c] = sc;
    shift[c] = beta[c % gmod] - mean * sc;
}

// ---------------- BN + ReLU + 2x2 maxpool ----------------
template<int C, int H, int W, int PAD>
__global__ void k_pool(const float* __restrict__ in, const float* __restrict__ scale,
                       const float* __restrict__ shift, float* __restrict__ out) {
    constexpr int HO = (H + 2 * PAD) / 2, WO = (W + 2 * PAD) / 2;
    int total = NB * C * HO * WO;
    for (int idx = blockIdx.x * blockDim.x + threadIdx.x; idx < total;
         idx += gridDim.x * blockDim.x) {
        int wo = idx % WO; int t = idx / WO;
        int ho = t % HO; t /= HO;
        int c = t % C; int b = t / C;
        const float* p = in + ((size_t)b * C + c) * (H * W);
        float sc = scale[c], sh = shift[c];
        float m = -1e30f;
        int iy0 = ho * 2 - PAD, ix0 = wo * 2 - PAD;
        #pragma unroll
        for (int dy = 0; dy < 2; dy++) {
            int iy = iy0 + dy; if (iy < 0 || iy >= H) continue;
            #pragma unroll
            for (int dx = 0; dx < 2; dx++) {
                int ix = ix0 + dx; if (ix < 0 || ix >= W) continue;
                float v = fmaxf(0.f, fmaf(p[iy * W + ix], sc, sh));
                if (v > m) m = v;
            }
        }
        out[idx] = m;
    }
}

// ---------------- NMS (rotation-minor channel view c = c1*8 + j) ----------------
__global__ void k_nms(const float* __restrict__ x, const float* __restrict__ scale,
                      const float* __restrict__ shift, float* __restrict__ nms_sum) {
    const int HW = 196;
    int total = NB * 4 * HW;
    float local = 0.f;
    for (int idx = blockIdx.x * blockDim.x + threadIdx.x; idx < total;
         idx += gridDim.x * blockDim.x) {
        int p = idx % HW; int t = idx / HW;
        int c1 = t % 4; int b = t / 4;
        const float* base = x + ((size_t)b * 32 + c1 * 8) * HW + p;
        float v[8]; float m = -1e30f;
        #pragma unroll
        for (int j = 0; j < 8; j++) {
            int c = c1 * 8 + j;
            float u = fmaxf(0.f, fmaf(base[j * HW], scale[c], shift[c]));
            v[j] = u; if (u > m) m = u;
        }
        float s = 0.f;
        #pragma unroll
        for (int j = 0; j < 8; j++) if (v[j] != m) s += v[j];
        local += s;
    }
    local = warp_sum(local);
    __shared__ float sh[8];
    int lane = threadIdx.x & 31, wid = threadIdx.x >> 5;
    if (lane == 0) sh[wid] = local;
    __syncthreads();
    if (threadIdx.x == 0) {
        float a = 0.f;
        #pragma unroll
        for (int i = 0; i < 8; i++) a += sh[i];
        atomicAdd(nms_sum, a);
    }
}

// ---------------- conv7 (4x4, pad 2) + bias + global maxpool + NMS scalar -----------
__global__ __launch_bounds__(256)
void k_conv7(const float* __restrict__ in, const float* __restrict__ w7,
             const float* __restrict__ b7, const float* __restrict__ nms_sum,
             float* __restrict__ out, int out_size) {
    __shared__ float s_in[64 * 16];
    __shared__ float s_w[10 * 64 * 16];
    __shared__ float s_res[250];
    __shared__ float s_b[10];
    int b = blockIdx.x, tid = threadIdx.x;
    for (int i = tid; i < 64 * 16; i += 256) s_in[i] = in[(size_t)b * 64 * 16 + i];
    for (int i = tid; i < 10 * 64 * 16; i += 256) s_w[i] = w7[i];
    if (tid < 10) s_b[tid] = b7[tid];
    __syncthreads();

    for (int item = tid; item < 250; item += 256) {
        int oc = item / 25; int pix = item % 25;
        int oy = pix / 5, ox = pix % 5;
        float a = 0.f;
        for (int ic = 0; ic < 64; ic++) {
            const float* ip = s_in + ic * 16;
            const float* wp = s_w + (oc * 64 + ic) * 16;
            #pragma unroll
            for (int ky = 0; ky < 4; ky++) {
                int iy = oy + ky - 2; if (iy < 0 || iy > 3) continue;
                #pragma unroll
                for (int kx = 0; kx < 4; kx++) {
                    int ix = ox + kx - 2; if (ix < 0 || ix > 3) continue;
                    a = fmaf(ip[iy * 4 + ix], wp[ky * 4 + kx], a);
                }
            }
        }
        s_res[item] = a;
    }
    __syncthreads();
    if (tid < 10) {
        float m = -1e30f;
        #pragma unroll
        for (int p = 0; p < 25; p++) m = fmaxf(m, s_res[tid * 25 + p]);
        out[b * 10 + tid] = m + s_b[tid];
    }
    if (b == 0 && tid == 0)
        out[out_size - 1] = nms_sum[0] * (1.0f / 12845056.0f);
}

// ---------------- launch ----------------
extern "C" void kernel_launch(void* const* d_in, const int* in_sizes, int n_in,
                              void* d_out, int out_size) {
    const float* x   = (const float*)d_in[0];
    const float* w1  = (const float*)d_in[1];
    const float* w2  = (const float*)d_in[2];
    const float* w3  = (const float*)d_in[3];
    const float* w4  = (const float*)d_in[4];
    const float* w5  = (const float*)d_in[5];
    const float* w6  = (const float*)d_in[6];
    const float* w7  = (const float*)d_in[7];
    const float* g1  = (const float*)d_in[8];
    const float* b1  = (const float*)d_in[9];
    const float* g2  = (const float*)d_in[10];
    const float* b2  = (const float*)d_in[11];
    const float* g3  = (const float*)d_in[12];
    const float* b3  = (const float*)d_in[13];
    const float* g4  = (const float*)d_in[14];
    const float* b4  = (const float*)d_in[15];
    const float* g5  = (const float*)d_in[16];
    const float* b5  = (const float*)d_in[17];
    const float* g6  = (const float*)d_in[18];
    const float* b6  = (const float*)d_in[19];
    const float* b7  = (const float*)d_in[20];
    float* out = (float*)d_out;

    float *buf1, *buf2, *buf3, *buf4, *buf5, *buf6, *buf7, *buf8, *buf9;
    float *rk1, *rk2, *rk3, *psum, *psumsq, *pscale, *pshift, *pnms;
    cudaGetSymbolAddress((void**)&buf1, g_buf1);
    cudaGetSymbolAddress((void**)&buf2, g_buf2);
    cudaGetSymbolAddress((void**)&buf3, g_buf3);
    cudaGetSymbolAddress((void**)&buf4, g_buf4);
    cudaGetSymbolAddress((void**)&buf5, g_buf5);
    cudaGetSymbolAddress((void**)&buf6, g_buf6);
    cudaGetSymbolAddress((void**)&buf7, g_buf7);
    cudaGetSymbolAddress((void**)&buf8, g_buf8);
    cudaGetSymbolAddress((void**)&buf9, g_buf9);
    cudaGetSymbolAddress((void**)&rk1, g_rk1);
    cudaGetSymbolAddress((void**)&rk2, g_rk2);
    cudaGetSymbolAddress((void**)&rk3, g_rk3);
    cudaGetSymbolAddress((void**)&psum, g_sum);
    cudaGetSymbolAddress((void**)&psumsq, g_sumsq);
    cudaGetSymbolAddress((void**)&pscale, g_scale);
    cudaGetSymbolAddress((void**)&pshift, g_shift);
    cudaGetSymbolAddress((void**)&pnms, g_nms);

    // smem sizes: (IMGS*CIN*HP*WP + CIN*COUT*9) * 4
    const int SM1 = (1*1*30*30  + 1*16*9)  * 4;   //   4176
    const int SM2 = (1*16*30*30 + 16*16*9) * 4;   //  66816
    const int SM3 = (1*16*16*18 + 16*32*9) * 4;   //  36864
    const int SM4 = (1*32*16*18 + 32*32*9) * 4;   //  73728
    const int SM5 = (2*32*9*10  + 32*64*9) * 4;   //  96768
    const int SM6 = (2*64*9*10  + 64*64*9) * 4;   // 193536

    cudaFuncSetAttribute(conv3x3f2<16,16,28,28,1,true>,  cudaFuncAttributeMaxDynamicSharedMemorySize, SM2);
    cudaFuncSetAttribute(conv3x3f2<32,32,14,14,1,true>,  cudaFuncAttributeMaxDynamicSharedMemorySize, SM4);
    cudaFuncSetAttribute(conv3x3f2<32,64,7,7,2,false>,   cudaFuncAttributeMaxDynamicSharedMemorySize, SM5);
    cudaFuncSetAttribute(conv3x3f2<64,64,7,7,2,true>,    cudaFuncAttributeMaxDynamicSharedMemorySize, SM6);

    const float invN784 = 1.0f / (2048.0f * 784.0f);
    const float invN196 = 1.0f / (2048.0f * 196.0f);
    const float invN49  = 1.0f / (2048.0f * 49.0f);

    k_zero<<<1, 256>>>();
    k_build_rk<<<4, 256>>>(w1, w2, w3);

    // layer 1
    conv3x3f2<1,16,28,28,1,false><<<NB, 256, SM1>>>(x, rk1, nullptr, nullptr, buf1);
    k_stats4<<<dim3(64, 16), 256>>>(buf1, psum + S1, psumsq + S1, 16, 196);
    k_finalize<<<1, 16>>>(psum + S1, psumsq + S1, g1, b1, pscale + S1, pshift + S1, 16, 2, invN784);

    // layer 2 (fused bn1+relu on input)
    conv3x3f2<16,16,28,28,1,true><<<NB, 256, SM2>>>(buf1, rk2, pscale + S1, pshift + S1, buf2);
    k_stats4<<<dim3(64, 16), 256>>>(buf2, psum + S2, psumsq + S2, 16, 196);
    k_finalize<<<1, 16>>>(psum + S2, psumsq + S2, g2, b2, pscale + S2, pshift + S2, 16, 2, invN784);

    // bn2+relu+pool
    k_pool<16,28,28,0><<<4096, 256>>>(buf2, pscale + S2, pshift + S2, buf3);

    // layer 3
    conv3x3f2<16,32,14,14,1,false><<<NB, 256, SM3>>>(buf3, rk3, nullptr, nullptr, buf4);
    k_stats4<<<dim3(64, 32), 256>>>(buf4, psum + S3, psumsq + S3, 32, 49);
    k_finalize<<<1, 32>>>(psum + S3, psumsq + S3, g3, b3, pscale + S3, pshift + S3, 32, 4, invN196);

    // nms on act3
    k_nms<<<1024, 256>>>(buf4, pscale + S3, pshift + S3, pnms);

    // layer 4 (fused bn3+relu)
    conv3x3f2<32,32,14,14,1,true><<<NB, 256, SM4>>>(buf4, w4, pscale + S3, pshift + S3, buf5);
    k_stats4<<<dim3(64, 32), 256>>>(buf5, psum + S4, psumsq + S4, 32, 49);
    k_finalize<<<1, 32>>>(psum + S4, psumsq + S4, g4, b4, pscale + S4, pshift + S4, 32, 32, invN196);

    // bn4+relu+pool
    k_pool<32,14,14,0><<<2048, 256>>>(buf5, pscale + S4, pshift + S4, buf6);

    // layer 5 (2 images/block)
    conv3x3f2<32,64,7,7,2,false><<<NB/2, 256, SM5>>>(buf6, w5, nullptr, nullptr, buf7);
    k_stats<<<dim3(64, 64), 256>>>(buf7, psum + S5, psumsq + S5, 64, 49);
    k_finalize<<<1, 64>>>(psum + S5, psumsq + S5, g5, b5, pscale + S5, pshift + S5, 64, 64, invN49);

    // layer 6 (fused bn5+relu, 2 images/block)
    conv3x3f2<64,64,7,7,2,true><<<NB/2, 256, SM6>>>(buf7, w6, pscale + S5, pshift + S5, buf8);
    k_stats<<<dim3(64, 64), 256>>>(buf8, psum + S6, psumsq + S6, 64, 49);
    k_finalize<<<1, 64>>>(psum + S6, psumsq + S6, g6, b6, pscale + S6, pshift + S6, 64, 64, invN49);

    // bn6+relu+pool(pad=1)
    k_pool<64,7,7,1><<<1024, 256>>>(buf8, pscale + S6, pshift + S6, buf9);

    // conv7 + bias + global maxpool + nms scalar
    k_conv7<<<NB, 256>>>(buf9, w7, b7, pnms, out, out_size);
}